// round 2
// baseline (speedup 1.0000x reference)
#include <cuda_runtime.h>
#include <cuda_bf16.h>
#include <math.h>

// Problem shape (fixed by dataset): B=4, N=M=4096, DF=16
#define BB 4
#define NN 4096
#define MM 4096
#define DF 16
#define MSPLIT 4
#define KM 128            // keys per smem tile
#define TPB 256           // threads per block (1 query row per thread)

#define BLUR 0.01f
#define LOG2E 1.4426950408889634f

// Scratch (no allocations allowed -> __device__ globals)
__device__ float4 g_keys[BB * MM * (DF / 4)];   // scaled key features: LOG2E*2*inv * tgt_fea
__device__ float4 g_vb[BB * MM];                // {tgt0, tgt1, tgt2, beta'}
__device__ float4 g_st[MSPLIT * BB * NN];       // per-row partial {S, T0, T1, T2}

__device__ __forceinline__ float ex2f(float x) {
    float r;
    asm("ex2.approx.ftz.f32 %0, %1;" : "=f"(r) : "f"(x));
    return r;
}

// ---------------------------------------------------------------------------
// Kernel 1: per-key precompute.
//   yy = inv * tgt_fea ; y2 = sum(yy^2)
//   k' = (2*LOG2E) * yy          (so q.k' = LOG2E * 2*xy with q = inv*src_fea)
//   beta' = LOG2E * (G_j/blur^2 - y2)
// ---------------------------------------------------------------------------
__global__ void prep_keys_kernel(const float* __restrict__ tgt,
                                 const float* __restrict__ tgt_fea,
                                 const float* __restrict__ G_j) {
    int g = blockIdx.x * blockDim.x + threadIdx.x;   // 0 .. B*M-1
    if (g >= BB * MM) return;
    const float inv = 1.0f / (1.41421356237f * BLUR);
    const float ksc = 2.0f * LOG2E;
    const float4* tf = reinterpret_cast<const float4*>(tgt_fea) + g * 4;
    float y2 = 0.0f;
    float4 o[4];
#pragma unroll
    for (int i = 0; i < 4; i++) {
        float4 v = tf[i];
        float a = inv * v.x, b = inv * v.y, c = inv * v.z, d = inv * v.w;
        y2 += a * a + b * b + c * c + d * d;
        o[i] = make_float4(ksc * a, ksc * b, ksc * c, ksc * d);
    }
#pragma unroll
    for (int i = 0; i < 4; i++) g_keys[g * 4 + i] = o[i];

    float beta = LOG2E * (G_j[g] * (1.0f / (BLUR * BLUR)) - y2);
    float v0 = tgt[g * 3 + 0];
    float v1 = tgt[g * 3 + 1];
    float v2 = tgt[g * 3 + 2];
    g_vb[g] = make_float4(v0, v1, v2, beta);
}

// ---------------------------------------------------------------------------
// Kernel 2: main pairwise loop (flash-attention style, no max needed).
// grid = (B * N/TPB, MSPLIT). Each thread owns one query row n, accumulates
// S = sum_m exp(logit), T = sum_m exp(logit)*tgt_m over its M-chunk.
// ---------------------------------------------------------------------------
__global__ __launch_bounds__(TPB) void ot_main_kernel(
    const float* __restrict__ src_fea, const float* __restrict__ F_i) {
    __shared__ float4 sk[KM * 4];
    __shared__ float4 svb[KM];

    const int b = blockIdx.x / (NN / TPB);
    const int nt = blockIdx.x % (NN / TPB);
    const int n = nt * TPB + threadIdx.x;
    const int gn = b * NN + n;

    const float inv = 1.0f / (1.41421356237f * BLUR);
    float q[16];
    float x2 = 0.0f;
    const float4* sf = reinterpret_cast<const float4*>(src_fea) + gn * 4;
#pragma unroll
    for (int i = 0; i < 4; i++) {
        float4 v = sf[i];
        float a = inv * v.x, bq = inv * v.y, c = inv * v.z, d = inv * v.w;
        q[4 * i + 0] = a; q[4 * i + 1] = bq; q[4 * i + 2] = c; q[4 * i + 3] = d;
        x2 += a * a + bq * bq + c * c + d * d;
    }
    const float alpha = LOG2E * (F_i[gn] * (1.0f / (BLUR * BLUR)) - x2);

    float S = 0.0f, T0 = 0.0f, T1 = 0.0f, T2 = 0.0f;
    const int m0 = blockIdx.y * (MM / MSPLIT);

    for (int mc = m0; mc < m0 + MM / MSPLIT; mc += KM) {
        __syncthreads();
        {
            const float4* gk = &g_keys[(b * MM + mc) * 4];
#pragma unroll
            for (int i = threadIdx.x; i < KM * 4; i += TPB) sk[i] = gk[i];
            const float4* gv = &g_vb[b * MM + mc];
            if (threadIdx.x < KM) svb[threadIdx.x] = gv[threadIdx.x];
        }
        __syncthreads();

#pragma unroll 4
        for (int j = 0; j < KM; j++) {
            float4 k0 = sk[j * 4 + 0];
            float4 k1 = sk[j * 4 + 1];
            float4 k2 = sk[j * 4 + 2];
            float4 k3 = sk[j * 4 + 3];
            float4 vb = svb[j];
            float d0 = fmaf(q[0], k0.x, fmaf(q[4], k1.x, fmaf(q[8],  k2.x, q[12] * k3.x)));
            float d1 = fmaf(q[1], k0.y, fmaf(q[5], k1.y, fmaf(q[9],  k2.y, q[13] * k3.y)));
            float d2 = fmaf(q[2], k0.z, fmaf(q[6], k1.z, fmaf(q[10], k2.z, q[14] * k3.z)));
            float d3 = fmaf(q[3], k0.w, fmaf(q[7], k1.w, fmaf(q[11], k2.w, q[15] * k3.w)));
            float arg = (alpha + vb.w) + ((d0 + d1) + (d2 + d3));
            float e = ex2f(arg);
            S += e;
            T0 = fmaf(e, vb.x, T0);
            T1 = fmaf(e, vb.y, T1);
            T2 = fmaf(e, vb.z, T2);
        }
    }
    g_st[(blockIdx.y * BB + b) * NN + n] = make_float4(S, T0, T1, T2);
}

// ---------------------------------------------------------------------------
// Kernel 3: per-batch reduction (23 fp64 sums) + 3x3 SVD (Jacobi) + Kabsch.
// One block per batch; deterministic fixed-order tree reduction.
// NOTE: the reference computes r = (u * c[:, :, None]) @ vh — c broadcasts
// over the LAST axis, i.e. it scales ROWS of u:  R = diag(1,1,det) · U · V^T,
// with det = det(U@V) = sign(det(A)).  U·V^T = u1v1'+u2v2'+sgn·(u1xu2)(v1xv2)'.
// ---------------------------------------------------------------------------
__global__ __launch_bounds__(256) void reduce_svd_kernel(
    const float* __restrict__ src, float* __restrict__ out) {
    const int b = blockIdx.x;
    double acc[23];
#pragma unroll
    for (int i = 0; i < 23; i++) acc[i] = 0.0;

    for (int n = threadIdx.x; n < NN; n += 256) {
        float Sf = 0.f, t0f = 0.f, t1f = 0.f, t2f = 0.f;
#pragma unroll
        for (int c = 0; c < MSPLIT; c++) {
            float4 p = g_st[(c * BB + b) * NN + n];
            Sf += p.x; t0f += p.y; t1f += p.z; t2f += p.w;
        }
        double S = Sf, T0 = t0f, T1 = t1f, T2 = t2f;
        double x0 = src[(b * NN + n) * 3 + 0];
        double x1 = src[(b * NN + n) * 3 + 1];
        double x2 = src[(b * NN + n) * 3 + 2];
        double S2 = S * S;
        acc[0] += S;
        acc[1] += S * x0;  acc[2] += S * x1;  acc[3] += S * x2;
        acc[4] += T0;      acc[5] += T1;      acc[6] += T2;
        acc[7] += S2;
        acc[8] += S2 * x0; acc[9] += S2 * x1; acc[10] += S2 * x2;
        acc[11] += S * T0; acc[12] += S * T1; acc[13] += S * T2;
        acc[14] += S * T0 * x0; acc[15] += S * T0 * x1; acc[16] += S * T0 * x2;
        acc[17] += S * T1 * x0; acc[18] += S * T1 * x1; acc[19] += S * T1 * x2;
        acc[20] += S * T2 * x0; acc[21] += S * T2 * x1; acc[22] += S * T2 * x2;
    }

    __shared__ double red[256];
    __shared__ double tot[23];
    for (int qd = 0; qd < 23; qd++) {
        red[threadIdx.x] = acc[qd];
        __syncthreads();
        for (int s = 128; s > 0; s >>= 1) {
            if (threadIdx.x < s) red[threadIdx.x] += red[threadIdx.x + s];
            __syncthreads();
        }
        if (threadIdx.x == 0) tot[qd] = red[0];
        __syncthreads();
    }

    if (threadIdx.x == 0) {
        double Sw = tot[0];
        double mux[3] = {tot[1] / Sw, tot[2] / Sw, tot[3] / Sw};
        double muy[3] = {tot[4] / Sw, tot[5] / Sw, tot[6] / Sw};
        double S2 = tot[7];
        double S2x[3] = {tot[8], tot[9], tot[10]};
        double STp[3] = {tot[11], tot[12], tot[13]};
        double A[3][3];
        for (int d = 0; d < 3; d++)
            for (int e = 0; e < 3; e++)
                A[d][e] = tot[14 + 3 * d + e] - mux[e] * STp[d]
                        - muy[d] * S2x[e] + muy[d] * mux[e] * S2;

        // sign(det(A)) = det(U@V)  (singular values are positive)
        double detA =
            A[0][0] * (A[1][1] * A[2][2] - A[1][2] * A[2][1])
          - A[0][1] * (A[1][0] * A[2][2] - A[1][2] * A[2][0])
          + A[0][2] * (A[1][0] * A[2][1] - A[1][1] * A[2][0]);
        double sgn = (detA >= 0.0) ? 1.0 : -1.0;

        // C = A^T A
        double C[3][3];
        for (int i = 0; i < 3; i++)
            for (int j = 0; j < 3; j++) {
                double s = 0.0;
                for (int d = 0; d < 3; d++) s += A[d][i] * A[d][j];
                C[i][j] = s;
            }
        // Jacobi eigendecomposition of C -> V, eigenvalues on diag(C)
        double V[3][3] = {{1,0,0},{0,1,0},{0,0,1}};
        const int pq[3][2] = {{0,1},{0,2},{1,2}};
        for (int sweep = 0; sweep < 15; sweep++) {
            for (int r = 0; r < 3; r++) {
                int p = pq[r][0], q = pq[r][1];
                double apq = C[p][q];
                if (fabs(apq) < 1e-30) continue;
                double theta = (C[q][q] - C[p][p]) / (2.0 * apq);
                double t = (theta >= 0.0 ? 1.0 : -1.0) /
                           (fabs(theta) + sqrt(1.0 + theta * theta));
                double c = 1.0 / sqrt(1.0 + t * t);
                double s = t * c;
                for (int k = 0; k < 3; k++) {
                    double ckp = C[k][p], ckq = C[k][q];
                    C[k][p] = c * ckp - s * ckq;
                    C[k][q] = s * ckp + c * ckq;
                }
                for (int k = 0; k < 3; k++) {
                    double cpk = C[p][k], cqk = C[q][k];
                    C[p][k] = c * cpk - s * cqk;
                    C[q][k] = s * cpk + c * cqk;
                }
                for (int k = 0; k < 3; k++) {
                    double vkp = V[k][p], vkq = V[k][q];
                    V[k][p] = c * vkp - s * vkq;
                    V[k][q] = s * vkp + c * vkq;
                }
            }
        }
        // sort eigenpairs (descending), take top-2
        double ev[3] = {C[0][0], C[1][1], C[2][2]};
        int i0 = 0;
        if (ev[1] > ev[i0]) i0 = 1;
        if (ev[2] > ev[i0]) i0 = 2;
        int i2 = 0;
        if (ev[1] < ev[i2]) i2 = 1;
        if (ev[2] < ev[i2]) i2 = 2;
        if (i2 == i0) i2 = (i0 + 1) % 3;
        int i1 = 3 - i0 - i2;

        double v1[3] = {V[0][i0], V[1][i0], V[2][i0]};
        double v2[3] = {V[0][i1], V[1][i1], V[2][i1]};
        // u1 = normalize(A v1)
        double u1[3], u2[3];
        for (int d = 0; d < 3; d++)
            u1[d] = A[d][0] * v1[0] + A[d][1] * v1[1] + A[d][2] * v1[2];
        double n1 = sqrt(u1[0]*u1[0] + u1[1]*u1[1] + u1[2]*u1[2]);
        for (int d = 0; d < 3; d++) u1[d] /= n1;
        // u2 = normalize(A v2 - (u1 . A v2) u1)
        for (int d = 0; d < 3; d++)
            u2[d] = A[d][0] * v2[0] + A[d][1] * v2[1] + A[d][2] * v2[2];
        double dp = u1[0]*u2[0] + u1[1]*u2[1] + u1[2]*u2[2];
        for (int d = 0; d < 3; d++) u2[d] -= dp * u1[d];
        double n2 = sqrt(u2[0]*u2[0] + u2[1]*u2[1] + u2[2]*u2[2]);
        for (int d = 0; d < 3; d++) u2[d] /= n2;
        // u3 = u1 x u2, v3 = v1 x v2; actual 3rd dyad u3'v3'^T = sgn * u3 v3^T
        double u3[3] = {u1[1]*u2[2] - u1[2]*u2[1],
                        u1[2]*u2[0] - u1[0]*u2[2],
                        u1[0]*u2[1] - u1[1]*u2[0]};
        double v3[3] = {v1[1]*v2[2] - v1[2]*v2[1],
                        v1[2]*v2[0] - v1[0]*v2[2],
                        v1[0]*v2[1] - v1[1]*v2[0]};
        // U V^T = u1 v1^T + u2 v2^T + sgn * u3 v3^T
        double UV[3][3];
        for (int d = 0; d < 3; d++)
            for (int e = 0; e < 3; e++)
                UV[d][e] = u1[d]*v1[e] + u2[d]*v2[e] + sgn * u3[d]*v3[e];
        // R = diag(1,1,sgn) * U V^T   (reference scales ROWS of u by c)
        double R[3][3];
        for (int d = 0; d < 3; d++) {
            double rs = (d == 2) ? sgn : 1.0;
            for (int e = 0; e < 3; e++) R[d][e] = rs * UV[d][e];
        }
        double tvec[3];
        for (int d = 0; d < 3; d++)
            tvec[d] = muy[d] - (R[d][0]*mux[0] + R[d][1]*mux[1] + R[d][2]*mux[2]);

        // output: rotation (B,3,3) flattened, then trans (B,3)
        for (int d = 0; d < 3; d++)
            for (int e = 0; e < 3; e++)
                out[b * 9 + d * 3 + e] = (float)R[d][e];
        for (int d = 0; d < 3; d++)
            out[BB * 9 + b * 3 + d] = (float)tvec[d];
    }
}

extern "C" void kernel_launch(void* const* d_in, const int* in_sizes, int n_in,
                              void* d_out, int out_size) {
    const float* src     = (const float*)d_in[0];
    const float* tgt     = (const float*)d_in[1];
    const float* src_fea = (const float*)d_in[2];
    const float* tgt_fea = (const float*)d_in[3];
    const float* F_i     = (const float*)d_in[4];
    const float* G_j     = (const float*)d_in[5];
    float* out = (float*)d_out;

    prep_keys_kernel<<<(BB * MM + 255) / 256, 256>>>(tgt, tgt_fea, G_j);
    dim3 grid(BB * (NN / TPB), MSPLIT);
    ot_main_kernel<<<grid, TPB>>>(src_fea, F_i);
    reduce_svd_kernel<<<BB, 256>>>(src, out);
}

// round 4
// speedup vs baseline: 1.3880x; 1.3880x over previous
#include <cuda_runtime.h>
#include <cuda_bf16.h>
#include <math.h>

// Problem shape (fixed by dataset): B=4, N=M=4096, DF=16
#define BB 4
#define NN 4096
#define MM 4096
#define DF 16
#define MSPLIT 8
#define KM 128            // keys per smem tile
#define TPB 128           // threads per block; each thread owns 2 query rows
#define QPB (TPB * 2)     // queries per block = 256

#define BLUR 0.01f
#define LOG2E 1.4426950408889634f

typedef unsigned long long u64;

// Scratch (no allocations allowed -> __device__ globals)
__device__ float4 g_keys[BB * MM * (DF / 4)];   // scaled keys: (2*LOG2E*inv) * tgt_fea, as f32x2 pairs
__device__ u64    g_vbx[BB * MM];               // pack(tgt0, tgt0)
__device__ u64    g_vby[BB * MM];               // pack(tgt1, tgt1)
__device__ u64    g_vbz[BB * MM];               // pack(tgt2, tgt2)
__device__ float  g_beta[BB * MM];              // LOG2E * (G/blur^2 - y2)
__device__ float4 g_st[MSPLIT * BB * NN];       // per-row partial {S, T0, T1, T2}

__device__ __forceinline__ float ex2f(float x) {
    float r;
    asm("ex2.approx.ftz.f32 %0, %1;" : "=f"(r) : "f"(x));
    return r;
}
__device__ __forceinline__ u64 pack2(float lo, float hi) {
    u64 r;
    asm("mov.b64 %0, {%1, %2};" : "=l"(r) : "f"(lo), "f"(hi));
    return r;
}
__device__ __forceinline__ void unpack2(u64 v, float& lo, float& hi) {
    asm("mov.b64 {%0, %1}, %2;" : "=f"(lo), "=f"(hi) : "l"(v));
}
__device__ __forceinline__ u64 fma2(u64 a, u64 b, u64 c) {
    u64 d;
    asm("fma.rn.f32x2 %0, %1, %2, %3;" : "=l"(d) : "l"(a), "l"(b), "l"(c));
    return d;
}
__device__ __forceinline__ u64 add2(u64 a, u64 b) {
    u64 d;
    asm("add.rn.f32x2 %0, %1, %2;" : "=l"(d) : "l"(a), "l"(b));
    return d;
}

// ---------------------------------------------------------------------------
// Kernel 1: per-key precompute.
// ---------------------------------------------------------------------------
__global__ void prep_keys_kernel(const float* __restrict__ tgt,
                                 const float* __restrict__ tgt_fea,
                                 const float* __restrict__ G_j) {
    int g = blockIdx.x * blockDim.x + threadIdx.x;   // 0 .. B*M-1
    if (g >= BB * MM) return;
    const float inv = 1.0f / (1.41421356237f * BLUR);
    const float ksc = 2.0f * LOG2E;
    const float4* tf = reinterpret_cast<const float4*>(tgt_fea) + g * 4;
    float y2 = 0.0f;
    float4 o[4];
#pragma unroll
    for (int i = 0; i < 4; i++) {
        float4 v = tf[i];
        float a = inv * v.x, b = inv * v.y, c = inv * v.z, d = inv * v.w;
        y2 += a * a + b * b + c * c + d * d;
        o[i] = make_float4(ksc * a, ksc * b, ksc * c, ksc * d);
    }
#pragma unroll
    for (int i = 0; i < 4; i++) g_keys[g * 4 + i] = o[i];

    g_beta[g] = LOG2E * (G_j[g] * (1.0f / (BLUR * BLUR)) - y2);
    float v0 = tgt[g * 3 + 0];
    float v1 = tgt[g * 3 + 1];
    float v2 = tgt[g * 3 + 2];
    g_vbx[g] = pack2(v0, v0);
    g_vby[g] = pack2(v1, v1);
    g_vbz[g] = pack2(v2, v2);
}

// ---------------------------------------------------------------------------
// Kernel 2: main pairwise loop. grid = (B * N/QPB, MSPLIT).
// Each thread owns 2 query rows (n, n+TPB); packed f32x2 math throughout.
// ---------------------------------------------------------------------------
__global__ __launch_bounds__(TPB) void ot_main_kernel(
    const float* __restrict__ src_fea, const float* __restrict__ F_i) {
    __shared__ float4 sk[KM * 4];       // keys, 4 x float4 = 8 f32x2 per key
    __shared__ u64    svx[KM];          // pack(tgt0,tgt0)
    __shared__ u64    svy[KM];
    __shared__ u64    svz[KM];
    __shared__ float  sbeta[KM];

    const int b  = blockIdx.x / (NN / QPB);
    const int nt = blockIdx.x % (NN / QPB);
    const int n0 = nt * QPB + threadIdx.x;      // query 0
    const int n1 = n0 + TPB;                    // query 1
    const int gn0 = b * NN + n0;
    const int gn1 = b * NN + n1;

    const float inv = 1.0f / (1.41421356237f * BLUR);

    // load + scale both query feature vectors, pack to f32x2
    u64 q0[8], q1[8];
    float alpha0, alpha1;
    {
        float x2 = 0.0f;
        const float4* sf = reinterpret_cast<const float4*>(src_fea) + gn0 * 4;
#pragma unroll
        for (int i = 0; i < 4; i++) {
            float4 v = sf[i];
            float a = inv * v.x, bq = inv * v.y, c = inv * v.z, d = inv * v.w;
            x2 += a * a + bq * bq + c * c + d * d;
            q0[2 * i + 0] = pack2(a, bq);
            q0[2 * i + 1] = pack2(c, d);
        }
        alpha0 = LOG2E * (F_i[gn0] * (1.0f / (BLUR * BLUR)) - x2);
    }
    {
        float x2 = 0.0f;
        const float4* sf = reinterpret_cast<const float4*>(src_fea) + gn1 * 4;
#pragma unroll
        for (int i = 0; i < 4; i++) {
            float4 v = sf[i];
            float a = inv * v.x, bq = inv * v.y, c = inv * v.z, d = inv * v.w;
            x2 += a * a + bq * bq + c * c + d * d;
            q1[2 * i + 0] = pack2(a, bq);
            q1[2 * i + 1] = pack2(c, d);
        }
        alpha1 = LOG2E * (F_i[gn1] * (1.0f / (BLUR * BLUR)) - x2);
    }

    u64 Sp  = 0ull;   // packed (S_q0,  S_q1)
    u64 T0p = 0ull;   // packed (T0_q0, T0_q1)
    u64 T1p = 0ull;
    u64 T2p = 0ull;

    const int m0 = blockIdx.y * (MM / MSPLIT);

    for (int mc = m0; mc < m0 + MM / MSPLIT; mc += KM) {
        __syncthreads();
        {
            const float4* gk = &g_keys[(b * MM + mc) * 4];
#pragma unroll
            for (int i = threadIdx.x; i < KM * 4; i += TPB) sk[i] = gk[i];
            if (threadIdx.x < KM) {
                int j = threadIdx.x;
                svx[j]   = g_vbx[b * MM + mc + j];
                svy[j]   = g_vby[b * MM + mc + j];
                svz[j]   = g_vbz[b * MM + mc + j];
                sbeta[j] = g_beta[b * MM + mc + j];
            }
        }
        __syncthreads();

#pragma unroll 4
        for (int j = 0; j < KM; j++) {
            const ulonglong2* kp = reinterpret_cast<const ulonglong2*>(&sk[j * 4]);
            float beta = sbeta[j];
            u64 acc0 = pack2(alpha0, beta);
            u64 acc1 = pack2(alpha1, beta);
#pragma unroll
            for (int i = 0; i < 2; i++) {
                ulonglong2 ka = kp[2 * i + 0];
                ulonglong2 kb = kp[2 * i + 1];
                acc0 = fma2(q0[4 * i + 0], ka.x, acc0);
                acc1 = fma2(q1[4 * i + 0], ka.x, acc1);
                acc0 = fma2(q0[4 * i + 1], ka.y, acc0);
                acc1 = fma2(q1[4 * i + 1], ka.y, acc1);
                acc0 = fma2(q0[4 * i + 2], kb.x, acc0);
                acc1 = fma2(q1[4 * i + 2], kb.x, acc1);
                acc0 = fma2(q0[4 * i + 3], kb.y, acc0);
                acc1 = fma2(q1[4 * i + 3], kb.y, acc1);
            }
            float l0, h0, l1, h1;
            unpack2(acc0, l0, h0);
            unpack2(acc1, l1, h1);
            float e0 = ex2f(l0 + h0);
            float e1 = ex2f(l1 + h1);
            u64 P = pack2(e0, e1);
            Sp  = add2(Sp, P);
            T0p = fma2(svx[j], P, T0p);
            T1p = fma2(svy[j], P, T1p);
            T2p = fma2(svz[j], P, T2p);
        }
    }

    float S0, S1, a0, a1, b0v, b1v, c0, c1;
    unpack2(Sp,  S0, S1);
    unpack2(T0p, a0, a1);
    unpack2(T1p, b0v, b1v);
    unpack2(T2p, c0, c1);
    g_st[(blockIdx.y * BB + b) * NN + n0] = make_float4(S0, a0, b0v, c0);
    g_st[(blockIdx.y * BB + b) * NN + n1] = make_float4(S1, a1, b1v, c1);
}

// ---------------------------------------------------------------------------
// Kernel 3: per-batch reduction (fp32 per-thread partials, fp64 tree) +
// 3x3 SVD (Jacobi) + Kabsch with reference's row-scaled reflection handling.
// ---------------------------------------------------------------------------
__global__ __launch_bounds__(256) void reduce_svd_kernel(
    const float* __restrict__ src, float* __restrict__ out) {
    const int b = blockIdx.x;
    float acc[23];
#pragma unroll
    for (int i = 0; i < 23; i++) acc[i] = 0.0f;

    for (int n = threadIdx.x; n < NN; n += 256) {
        float S = 0.f, T0 = 0.f, T1 = 0.f, T2 = 0.f;
#pragma unroll
        for (int c = 0; c < MSPLIT; c++) {
            float4 p = g_st[(c * BB + b) * NN + n];
            S += p.x; T0 += p.y; T1 += p.z; T2 += p.w;
        }
        float x0 = src[(b * NN + n) * 3 + 0];
        float x1 = src[(b * NN + n) * 3 + 1];
        float x2 = src[(b * NN + n) * 3 + 2];
        float S2 = S * S;
        acc[0] += S;
        acc[1] += S * x0;  acc[2] += S * x1;  acc[3] += S * x2;
        acc[4] += T0;      acc[5] += T1;      acc[6] += T2;
        acc[7] += S2;
        acc[8] += S2 * x0; acc[9] += S2 * x1; acc[10] += S2 * x2;
        acc[11] += S * T0; acc[12] += S * T1; acc[13] += S * T2;
        acc[14] += S * T0 * x0; acc[15] += S * T0 * x1; acc[16] += S * T0 * x2;
        acc[17] += S * T1 * x0; acc[18] += S * T1 * x1; acc[19] += S * T1 * x2;
        acc[20] += S * T2 * x0; acc[21] += S * T2 * x1; acc[22] += S * T2 * x2;
    }

    __shared__ double red[256];
    __shared__ double tot[23];
    for (int qd = 0; qd < 23; qd++) {
        red[threadIdx.x] = (double)acc[qd];
        __syncthreads();
        for (int s = 128; s > 0; s >>= 1) {
            if (threadIdx.x < s) red[threadIdx.x] += red[threadIdx.x + s];
            __syncthreads();
        }
        if (threadIdx.x == 0) tot[qd] = red[0];
        __syncthreads();
    }

    if (threadIdx.x == 0) {
        double Sw = tot[0];
        double mux[3] = {tot[1] / Sw, tot[2] / Sw, tot[3] / Sw};
        double muy[3] = {tot[4] / Sw, tot[5] / Sw, tot[6] / Sw};
        double S2 = tot[7];
        double S2x[3] = {tot[8], tot[9], tot[10]};
        double STp[3] = {tot[11], tot[12], tot[13]};
        double A[3][3];
        for (int d = 0; d < 3; d++)
            for (int e = 0; e < 3; e++)
                A[d][e] = tot[14 + 3 * d + e] - mux[e] * STp[d]
                        - muy[d] * S2x[e] + muy[d] * mux[e] * S2;

        // sign(det(A)) = det(U@V)  (singular values are positive)
        double detA =
            A[0][0] * (A[1][1] * A[2][2] - A[1][2] * A[2][1])
          - A[0][1] * (A[1][0] * A[2][2] - A[1][2] * A[2][0])
          + A[0][2] * (A[1][0] * A[2][1] - A[1][1] * A[2][0]);
        double sgn = (detA >= 0.0) ? 1.0 : -1.0;

        // C = A^T A
        double C[3][3];
        for (int i = 0; i < 3; i++)
            for (int j = 0; j < 3; j++) {
                double s = 0.0;
                for (int d = 0; d < 3; d++) s += A[d][i] * A[d][j];
                C[i][j] = s;
            }
        // Jacobi eigendecomposition of C -> V, eigenvalues on diag(C)
        double V[3][3] = {{1,0,0},{0,1,0},{0,0,1}};
        const int pq[3][2] = {{0,1},{0,2},{1,2}};
        for (int sweep = 0; sweep < 15; sweep++) {
            for (int r = 0; r < 3; r++) {
                int p = pq[r][0], q = pq[r][1];
                double apq = C[p][q];
                if (fabs(apq) < 1e-30) continue;
                double theta = (C[q][q] - C[p][p]) / (2.0 * apq);
                double t = (theta >= 0.0 ? 1.0 : -1.0) /
                           (fabs(theta) + sqrt(1.0 + theta * theta));
                double c = 1.0 / sqrt(1.0 + t * t);
                double s = t * c;
                for (int k = 0; k < 3; k++) {
                    double ckp = C[k][p], ckq = C[k][q];
                    C[k][p] = c * ckp - s * ckq;
                    C[k][q] = s * ckp + c * ckq;
                }
                for (int k = 0; k < 3; k++) {
                    double cpk = C[p][k], cqk = C[q][k];
                    C[p][k] = c * cpk - s * cqk;
                    C[q][k] = s * cpk + c * cqk;
                }
                for (int k = 0; k < 3; k++) {
                    double vkp = V[k][p], vkq = V[k][q];
                    V[k][p] = c * vkp - s * vkq;
                    V[k][q] = s * vkp + c * vkq;
                }
            }
        }
        // sort eigenpairs (descending), take top-2
        double ev[3] = {C[0][0], C[1][1], C[2][2]};
        int i0 = 0;
        if (ev[1] > ev[i0]) i0 = 1;
        if (ev[2] > ev[i0]) i0 = 2;
        int i2 = 0;
        if (ev[1] < ev[i2]) i2 = 1;
        if (ev[2] < ev[i2]) i2 = 2;
        if (i2 == i0) i2 = (i0 + 1) % 3;
        int i1 = 3 - i0 - i2;

        double v1[3] = {V[0][i0], V[1][i0], V[2][i0]};
        double v2[3] = {V[0][i1], V[1][i1], V[2][i1]};
        // u1 = normalize(A v1)
        double u1[3], u2[3];
        for (int d = 0; d < 3; d++)
            u1[d] = A[d][0] * v1[0] + A[d][1] * v1[1] + A[d][2] * v1[2];
        double n1 = sqrt(u1[0]*u1[0] + u1[1]*u1[1] + u1[2]*u1[2]);
        for (int d = 0; d < 3; d++) u1[d] /= n1;
        // u2 = normalize(A v2 - (u1 . A v2) u1)
        for (int d = 0; d < 3; d++)
            u2[d] = A[d][0] * v2[0] + A[d][1] * v2[1] + A[d][2] * v2[2];
        double dp = u1[0]*u2[0] + u1[1]*u2[1] + u1[2]*u2[2];
        for (int d = 0; d < 3; d++) u2[d] -= dp * u1[d];
        double n2 = sqrt(u2[0]*u2[0] + u2[1]*u2[1] + u2[2]*u2[2]);
        for (int d = 0; d < 3; d++) u2[d] /= n2;
        // u3 = u1 x u2, v3 = v1 x v2; actual 3rd dyad u3'v3'^T = sgn * u3 v3^T
        double u3[3] = {u1[1]*u2[2] - u1[2]*u2[1],
                        u1[2]*u2[0] - u1[0]*u2[2],
                        u1[0]*u2[1] - u1[1]*u2[0]};
        double v3[3] = {v1[1]*v2[2] - v1[2]*v2[1],
                        v1[2]*v2[0] - v1[0]*v2[2],
                        v1[0]*v2[1] - v1[1]*v2[0]};
        // U V^T = u1 v1^T + u2 v2^T + sgn * u3 v3^T
        double UV[3][3];
        for (int d = 0; d < 3; d++)
            for (int e = 0; e < 3; e++)
                UV[d][e] = u1[d]*v1[e] + u2[d]*v2[e] + sgn * u3[d]*v3[e];
        // R = diag(1,1,sgn) * U V^T   (reference scales ROWS of u by c)
        double R[3][3];
        for (int d = 0; d < 3; d++) {
            double rs = (d == 2) ? sgn : 1.0;
            for (int e = 0; e < 3; e++) R[d][e] = rs * UV[d][e];
        }
        double tvec[3];
        for (int d = 0; d < 3; d++)
            tvec[d] = muy[d] - (R[d][0]*mux[0] + R[d][1]*mux[1] + R[d][2]*mux[2]);

        // output: rotation (B,3,3) flattened, then trans (B,3)
        for (int d = 0; d < 3; d++)
            for (int e = 0; e < 3; e++)
                out[b * 9 + d * 3 + e] = (float)R[d][e];
        for (int d = 0; d < 3; d++)
            out[BB * 9 + b * 3 + d] = (float)tvec[d];
    }
}

extern "C" void kernel_launch(void* const* d_in, const int* in_sizes, int n_in,
                              void* d_out, int out_size) {
    const float* src     = (const float*)d_in[0];
    const float* tgt     = (const float*)d_in[1];
    const float* src_fea = (const float*)d_in[2];
    const float* tgt_fea = (const float*)d_in[3];
    const float* F_i     = (const float*)d_in[4];
    const float* G_j     = (const float*)d_in[5];
    float* out = (float*)d_out;

    prep_keys_kernel<<<(BB * MM + 255) / 256, 256>>>(tgt, tgt_fea, G_j);
    dim3 grid(BB * (NN / QPB), MSPLIT);
    ot_main_kernel<<<grid, TPB>>>(src_fea, F_i);
    reduce_svd_kernel<<<BB, 256>>>(src, out);
}

// round 5
// speedup vs baseline: 1.4371x; 1.0353x over previous
#include <cuda_runtime.h>
#include <cuda_bf16.h>
#include <math.h>

// Problem shape (fixed by dataset): B=4, N=M=4096, DF=16
#define BB 4
#define NN 4096
#define MM 4096
#define DF 16
#define MSPLIT 16
#define KM 256            // keys per block tile == MM/MSPLIT (one tile per block)
#define TPB 128           // threads per block; each thread owns 2 query rows
#define QPB (TPB * 2)     // queries per block = 256

#define BLUR 0.01f
#define LOG2E 1.4426950408889634f

typedef unsigned long long u64;

// Scratch (no allocations allowed -> __device__ globals)
__device__ float4     g_keys[BB * MM * (DF / 4)];  // scaled keys
__device__ ulonglong2 g_vxy[BB * MM];              // {pack(v0,v0), pack(v1,v1)}
__device__ ulonglong2 g_vzb[BB * MM];              // {pack(v2,v2), pack(beta,beta)}
__device__ float4     g_st[MSPLIT * BB * NN];      // per-row partial {S, T0, T1, T2}

__device__ __forceinline__ float ex2f(float x) {
    float r;
    asm("ex2.approx.ftz.f32 %0, %1;" : "=f"(r) : "f"(x));
    return r;
}
__device__ __forceinline__ u64 pack2(float lo, float hi) {
    u64 r;
    asm("mov.b64 %0, {%1, %2};" : "=l"(r) : "f"(lo), "f"(hi));
    return r;
}
__device__ __forceinline__ void unpack2(u64 v, float& lo, float& hi) {
    asm("mov.b64 {%0, %1}, %2;" : "=f"(lo), "=f"(hi) : "l"(v));
}
__device__ __forceinline__ u64 fma2(u64 a, u64 b, u64 c) {
    u64 d;
    asm("fma.rn.f32x2 %0, %1, %2, %3;" : "=l"(d) : "l"(a), "l"(b), "l"(c));
    return d;
}
__device__ __forceinline__ u64 add2(u64 a, u64 b) {
    u64 d;
    asm("add.rn.f32x2 %0, %1, %2;" : "=l"(d) : "l"(a), "l"(b));
    return d;
}

// ---------------------------------------------------------------------------
// Kernel 1: per-key precompute.
//   k' = (2*LOG2E*inv) * tgt_fea;  beta = LOG2E*(G/blur^2 - |inv*tgt_fea|^2)
// ---------------------------------------------------------------------------
__global__ void prep_keys_kernel(const float* __restrict__ tgt,
                                 const float* __restrict__ tgt_fea,
                                 const float* __restrict__ G_j) {
    int g = blockIdx.x * blockDim.x + threadIdx.x;   // 0 .. B*M-1
    if (g >= BB * MM) return;
    const float inv = 1.0f / (1.41421356237f * BLUR);
    const float ksc = 2.0f * LOG2E;
    const float4* tf = reinterpret_cast<const float4*>(tgt_fea) + g * 4;
    float y2 = 0.0f;
    float4 o[4];
#pragma unroll
    for (int i = 0; i < 4; i++) {
        float4 v = tf[i];
        float a = inv * v.x, b = inv * v.y, c = inv * v.z, d = inv * v.w;
        y2 += a * a + b * b + c * c + d * d;
        o[i] = make_float4(ksc * a, ksc * b, ksc * c, ksc * d);
    }
#pragma unroll
    for (int i = 0; i < 4; i++) g_keys[g * 4 + i] = o[i];

    float beta = LOG2E * (G_j[g] * (1.0f / (BLUR * BLUR)) - y2);
    float v0 = tgt[g * 3 + 0];
    float v1 = tgt[g * 3 + 1];
    float v2 = tgt[g * 3 + 2];
    ulonglong2 xy, zb;
    xy.x = pack2(v0, v0);
    xy.y = pack2(v1, v1);
    zb.x = pack2(v2, v2);
    zb.y = pack2(beta, beta);
    g_vxy[g] = xy;
    g_vzb[g] = zb;
}

// ---------------------------------------------------------------------------
// Kernel 2: main pairwise loop. grid = (B * N/QPB, MSPLIT), one key tile per
// block (KM = MM/MSPLIT). Each thread owns 2 query rows (n, n+TPB); packed
// f32x2 math throughout.
// ---------------------------------------------------------------------------
__global__ __launch_bounds__(TPB, 8) void ot_main_kernel(
    const float* __restrict__ src_fea, const float* __restrict__ F_i) {
    __shared__ float4     sk[KM * 4];    // keys: 4 x float4 = 8 f32x2 per key
    __shared__ ulonglong2 sxy[KM];       // {pack(v0,v0), pack(v1,v1)}
    __shared__ ulonglong2 szb[KM];       // {pack(v2,v2), pack(beta,beta)}

    const int b  = blockIdx.x / (NN / QPB);
    const int nt = blockIdx.x % (NN / QPB);
    const int n0 = nt * QPB + threadIdx.x;      // query 0
    const int n1 = n0 + TPB;                    // query 1
    const int gn0 = b * NN + n0;
    const int gn1 = b * NN + n1;
    const int m0 = blockIdx.y * KM;

    // cooperative tile load (single tile for whole block lifetime)
    {
        const float4* gk = &g_keys[(b * MM + m0) * 4];
#pragma unroll
        for (int i = threadIdx.x; i < KM * 4; i += TPB) sk[i] = gk[i];
        const ulonglong2* gxy = &g_vxy[b * MM + m0];
        const ulonglong2* gzb = &g_vzb[b * MM + m0];
#pragma unroll
        for (int i = threadIdx.x; i < KM; i += TPB) {
            sxy[i] = gxy[i];
            szb[i] = gzb[i];
        }
    }

    const float inv = 1.0f / (1.41421356237f * BLUR);

    // load + scale both query feature vectors, pack to f32x2
    u64 q0[8], q1[8];
    float alpha0, alpha1;
    {
        float x2 = 0.0f;
        const float4* sf = reinterpret_cast<const float4*>(src_fea) + gn0 * 4;
#pragma unroll
        for (int i = 0; i < 4; i++) {
            float4 v = sf[i];
            float a = inv * v.x, bq = inv * v.y, c = inv * v.z, d = inv * v.w;
            x2 += a * a + bq * bq + c * c + d * d;
            q0[2 * i + 0] = pack2(a, bq);
            q0[2 * i + 1] = pack2(c, d);
        }
        alpha0 = LOG2E * (F_i[gn0] * (1.0f / (BLUR * BLUR)) - x2);
    }
    {
        float x2 = 0.0f;
        const float4* sf = reinterpret_cast<const float4*>(src_fea) + gn1 * 4;
#pragma unroll
        for (int i = 0; i < 4; i++) {
            float4 v = sf[i];
            float a = inv * v.x, bq = inv * v.y, c = inv * v.z, d = inv * v.w;
            x2 += a * a + bq * bq + c * c + d * d;
            q1[2 * i + 0] = pack2(a, bq);
            q1[2 * i + 1] = pack2(c, d);
        }
        alpha1 = LOG2E * (F_i[gn1] * (1.0f / (BLUR * BLUR)) - x2);
    }

    u64 Sp  = 0ull;   // packed (S_q0,  S_q1)
    u64 T0p = 0ull;   // packed (T0_q0, T0_q1)
    u64 T1p = 0ull;
    u64 T2p = 0ull;

    __syncthreads();

#pragma unroll 4
    for (int j = 0; j < KM; j++) {
        const ulonglong2* kp = reinterpret_cast<const ulonglong2*>(&sk[j * 4]);
        ulonglong2 zb = szb[j];
        float beta, bdup;
        unpack2(zb.y, beta, bdup);
        u64 acc0 = pack2(alpha0, beta);
        u64 acc1 = pack2(alpha1, beta);
#pragma unroll
        for (int i = 0; i < 2; i++) {
            ulonglong2 ka = kp[2 * i + 0];
            ulonglong2 kb = kp[2 * i + 1];
            acc0 = fma2(q0[4 * i + 0], ka.x, acc0);
            acc1 = fma2(q1[4 * i + 0], ka.x, acc1);
            acc0 = fma2(q0[4 * i + 1], ka.y, acc0);
            acc1 = fma2(q1[4 * i + 1], ka.y, acc1);
            acc0 = fma2(q0[4 * i + 2], kb.x, acc0);
            acc1 = fma2(q1[4 * i + 2], kb.x, acc1);
            acc0 = fma2(q0[4 * i + 3], kb.y, acc0);
            acc1 = fma2(q1[4 * i + 3], kb.y, acc1);
        }
        float l0, h0, l1, h1;
        unpack2(acc0, l0, h0);
        unpack2(acc1, l1, h1);
        float e0 = ex2f(l0 + h0);
        float e1 = ex2f(l1 + h1);
        u64 P = pack2(e0, e1);
        ulonglong2 xy = sxy[j];
        Sp  = add2(Sp, P);
        T0p = fma2(xy.x, P, T0p);
        T1p = fma2(xy.y, P, T1p);
        T2p = fma2(zb.x, P, T2p);
    }

    float S0, S1, a0, a1, b0v, b1v, c0, c1;
    unpack2(Sp,  S0, S1);
    unpack2(T0p, a0, a1);
    unpack2(T1p, b0v, b1v);
    unpack2(T2p, c0, c1);
    g_st[(blockIdx.y * BB + b) * NN + n0] = make_float4(S0, a0, b0v, c0);
    g_st[(blockIdx.y * BB + b) * NN + n1] = make_float4(S1, a1, b1v, c1);
}

// ---------------------------------------------------------------------------
// Kernel 3: per-batch reduction (fp32 per-thread partials, fp64 tree) +
// 3x3 SVD (Jacobi) + Kabsch with reference's row-scaled reflection handling.
// ---------------------------------------------------------------------------
__global__ __launch_bounds__(256) void reduce_svd_kernel(
    const float* __restrict__ src, float* __restrict__ out) {
    const int b = blockIdx.x;
    float acc[23];
#pragma unroll
    for (int i = 0; i < 23; i++) acc[i] = 0.0f;

    for (int n = threadIdx.x; n < NN; n += 256) {
        float S = 0.f, T0 = 0.f, T1 = 0.f, T2 = 0.f;
#pragma unroll
        for (int c = 0; c < MSPLIT; c++) {
            float4 p = g_st[(c * BB + b) * NN + n];
            S += p.x; T0 += p.y; T1 += p.z; T2 += p.w;
        }
        float x0 = src[(b * NN + n) * 3 + 0];
        float x1 = src[(b * NN + n) * 3 + 1];
        float x2 = src[(b * NN + n) * 3 + 2];
        float S2 = S * S;
        acc[0] += S;
        acc[1] += S * x0;  acc[2] += S * x1;  acc[3] += S * x2;
        acc[4] += T0;      acc[5] += T1;      acc[6] += T2;
        acc[7] += S2;
        acc[8] += S2 * x0; acc[9] += S2 * x1; acc[10] += S2 * x2;
        acc[11] += S * T0; acc[12] += S * T1; acc[13] += S * T2;
        acc[14] += S * T0 * x0; acc[15] += S * T0 * x1; acc[16] += S * T0 * x2;
        acc[17] += S * T1 * x0; acc[18] += S * T1 * x1; acc[19] += S * T1 * x2;
        acc[20] += S * T2 * x0; acc[21] += S * T2 * x1; acc[22] += S * T2 * x2;
    }

    __shared__ double red[256];
    __shared__ double tot[23];
    for (int qd = 0; qd < 23; qd++) {
        red[threadIdx.x] = (double)acc[qd];
        __syncthreads();
        for (int s = 128; s > 0; s >>= 1) {
            if (threadIdx.x < s) red[threadIdx.x] += red[threadIdx.x + s];
            __syncthreads();
        }
        if (threadIdx.x == 0) tot[qd] = red[0];
        __syncthreads();
    }

    if (threadIdx.x == 0) {
        double Sw = tot[0];
        double mux[3] = {tot[1] / Sw, tot[2] / Sw, tot[3] / Sw};
        double muy[3] = {tot[4] / Sw, tot[5] / Sw, tot[6] / Sw};
        double S2 = tot[7];
        double S2x[3] = {tot[8], tot[9], tot[10]};
        double STp[3] = {tot[11], tot[12], tot[13]};
        double A[3][3];
        for (int d = 0; d < 3; d++)
            for (int e = 0; e < 3; e++)
                A[d][e] = tot[14 + 3 * d + e] - mux[e] * STp[d]
                        - muy[d] * S2x[e] + muy[d] * mux[e] * S2;

        // sign(det(A)) = det(U@V)  (singular values are positive)
        double detA =
            A[0][0] * (A[1][1] * A[2][2] - A[1][2] * A[2][1])
          - A[0][1] * (A[1][0] * A[2][2] - A[1][2] * A[2][0])
          + A[0][2] * (A[1][0] * A[2][1] - A[1][1] * A[2][0]);
        double sgn = (detA >= 0.0) ? 1.0 : -1.0;

        // C = A^T A
        double C[3][3];
        for (int i = 0; i < 3; i++)
            for (int j = 0; j < 3; j++) {
                double s = 0.0;
                for (int d = 0; d < 3; d++) s += A[d][i] * A[d][j];
                C[i][j] = s;
            }
        // Jacobi eigendecomposition of C -> V, eigenvalues on diag(C)
        double V[3][3] = {{1,0,0},{0,1,0},{0,0,1}};
        const int pq[3][2] = {{0,1},{0,2},{1,2}};
        for (int sweep = 0; sweep < 15; sweep++) {
            for (int r = 0; r < 3; r++) {
                int p = pq[r][0], q = pq[r][1];
                double apq = C[p][q];
                if (fabs(apq) < 1e-30) continue;
                double theta = (C[q][q] - C[p][p]) / (2.0 * apq);
                double t = (theta >= 0.0 ? 1.0 : -1.0) /
                           (fabs(theta) + sqrt(1.0 + theta * theta));
                double c = 1.0 / sqrt(1.0 + t * t);
                double s = t * c;
                for (int k = 0; k < 3; k++) {
                    double ckp = C[k][p], ckq = C[k][q];
                    C[k][p] = c * ckp - s * ckq;
                    C[k][q] = s * ckp + c * ckq;
                }
                for (int k = 0; k < 3; k++) {
                    double cpk = C[p][k], cqk = C[q][k];
                    C[p][k] = c * cpk - s * cqk;
                    C[q][k] = s * cpk + c * cqk;
                }
                for (int k = 0; k < 3; k++) {
                    double vkp = V[k][p], vkq = V[k][q];
                    V[k][p] = c * vkp - s * vkq;
                    V[k][q] = s * vkp + c * vkq;
                }
            }
        }
        // sort eigenpairs (descending), take top-2
        double ev[3] = {C[0][0], C[1][1], C[2][2]};
        int i0 = 0;
        if (ev[1] > ev[i0]) i0 = 1;
        if (ev[2] > ev[i0]) i0 = 2;
        int i2 = 0;
        if (ev[1] < ev[i2]) i2 = 1;
        if (ev[2] < ev[i2]) i2 = 2;
        if (i2 == i0) i2 = (i0 + 1) % 3;
        int i1 = 3 - i0 - i2;

        double v1[3] = {V[0][i0], V[1][i0], V[2][i0]};
        double v2[3] = {V[0][i1], V[1][i1], V[2][i1]};
        // u1 = normalize(A v1)
        double u1[3], u2[3];
        for (int d = 0; d < 3; d++)
            u1[d] = A[d][0] * v1[0] + A[d][1] * v1[1] + A[d][2] * v1[2];
        double n1 = sqrt(u1[0]*u1[0] + u1[1]*u1[1] + u1[2]*u1[2]);
        for (int d = 0; d < 3; d++) u1[d] /= n1;
        // u2 = normalize(A v2 - (u1 . A v2) u1)
        for (int d = 0; d < 3; d++)
            u2[d] = A[d][0] * v2[0] + A[d][1] * v2[1] + A[d][2] * v2[2];
        double dp = u1[0]*u2[0] + u1[1]*u2[1] + u1[2]*u2[2];
        for (int d = 0; d < 3; d++) u2[d] -= dp * u1[d];
        double n2 = sqrt(u2[0]*u2[0] + u2[1]*u2[1] + u2[2]*u2[2]);
        for (int d = 0; d < 3; d++) u2[d] /= n2;
        // u3 = u1 x u2, v3 = v1 x v2; actual 3rd dyad u3'v3'^T = sgn * u3 v3^T
        double u3[3] = {u1[1]*u2[2] - u1[2]*u2[1],
                        u1[2]*u2[0] - u1[0]*u2[2],
                        u1[0]*u2[1] - u1[1]*u2[0]};
        double v3[3] = {v1[1]*v2[2] - v1[2]*v2[1],
                        v1[2]*v2[0] - v1[0]*v2[2],
                        v1[0]*v2[1] - v1[1]*v2[0]};
        // U V^T = u1 v1^T + u2 v2^T + sgn * u3 v3^T
        double UV[3][3];
        for (int d = 0; d < 3; d++)
            for (int e = 0; e < 3; e++)
                UV[d][e] = u1[d]*v1[e] + u2[d]*v2[e] + sgn * u3[d]*v3[e];
        // R = diag(1,1,sgn) * U V^T   (reference scales ROWS of u by c)
        double R[3][3];
        for (int d = 0; d < 3; d++) {
            double rs = (d == 2) ? sgn : 1.0;
            for (int e = 0; e < 3; e++) R[d][e] = rs * UV[d][e];
        }
        double tvec[3];
        for (int d = 0; d < 3; d++)
            tvec[d] = muy[d] - (R[d][0]*mux[0] + R[d][1]*mux[1] + R[d][2]*mux[2]);

        // output: rotation (B,3,3) flattened, then trans (B,3)
        for (int d = 0; d < 3; d++)
            for (int e = 0; e < 3; e++)
                out[b * 9 + d * 3 + e] = (float)R[d][e];
        for (int d = 0; d < 3; d++)
            out[BB * 9 + b * 3 + d] = (float)tvec[d];
    }
}

extern "C" void kernel_launch(void* const* d_in, const int* in_sizes, int n_in,
                              void* d_out, int out_size) {
    const float* src     = (const float*)d_in[0];
    const float* tgt     = (const float*)d_in[1];
    const float* src_fea = (const float*)d_in[2];
    const float* tgt_fea = (const float*)d_in[3];
    const float* F_i     = (const float*)d_in[4];
    const float* G_j     = (const float*)d_in[5];
    float* out = (float*)d_out;

    prep_keys_kernel<<<(BB * MM + 255) / 256, 256>>>(tgt, tgt_fea, G_j);
    dim3 grid(BB * (NN / QPB), MSPLIT);
    ot_main_kernel<<<grid, TPB>>>(src_fea, F_i);
    reduce_svd_kernel<<<BB, 256>>>(src, out);
}

// round 8
// speedup vs baseline: 1.5070x; 1.0487x over previous
#include <cuda_runtime.h>
#include <cuda_bf16.h>
#include <math.h>
#include <cstdint>

// Problem shape (fixed by dataset): B=4, N=M=4096, DF=16
#define BB 4
#define NN 4096
#define MM 4096
#define KDL 56           // logical K dim (48 split dims + 4 aug + 4 pad)
#define RS 60            // smem B row stride in words (bank-spread + 16B align)
#define KC 256           // keys per smem chunk
#define KSPLIT 2         // key splits (2048 keys per CTA)
#define NCHK ((MM / KSPLIT) / KC)   // 8 chunks
#define TPB 256          // 8 warps * m32 = 256 queries per CTA

#define BLUR 0.01f
#define LOG2E 1.4426950408889634f

// -------- scratch (device globals; no allocations allowed) --------
__device__ __align__(16) float g_A[BB * NN * KDL];    // query rows, tf32-split, permuted
__device__ __align__(16) float g_B[BB * MM * KDL];    // key rows, same layout
__device__ __align__(16) float g_V[BB * MM * 8];      // Vaug rows: {1, vhi0..2, 0, vlo0..2}
__device__ __align__(16) float4 g_st[KSPLIT * BB * NN]; // per-query partials {S,T0,T1,T2}

__device__ __forceinline__ float ex2f(float x) {
    float r;
    asm("ex2.approx.ftz.f32 %0, %1;" : "=f"(r) : "f"(x));
    return r;
}
__device__ __forceinline__ float tf32r(float x) {
    uint32_t r;
    asm("cvt.rna.tf32.f32 %0, %1;" : "=r"(r) : "f"(x));
    return __uint_as_float(r);
}
__device__ __forceinline__ uint32_t smem_u32(const void* p) {
    uint32_t a;
    asm("{ .reg .u64 t; cvta.to.shared.u64 t, %1; cvt.u32.u64 %0, t; }" : "=r"(a) : "l"(p));
    return a;
}
__device__ __forceinline__ void cpa16(uint32_t dst, const void* src) {
    asm volatile("cp.async.cg.shared.global [%0], [%1], 16;" :: "r"(dst), "l"(src));
}
#define CP_COMMIT() asm volatile("cp.async.commit_group;" ::: "memory")
#define CP_WAIT(n)  asm volatile("cp.async.wait_group %0;" :: "n"(n) : "memory")

// m16n8k8 tf32 MMA, accumulate in place
__device__ __forceinline__ void mma8(float* d, const uint32_t* a, uint32_t b0, uint32_t b1) {
    asm volatile(
        "mma.sync.aligned.m16n8k8.row.col.f32.tf32.tf32.f32 "
        "{%0,%1,%2,%3}, {%4,%5,%6,%7}, {%8,%9}, {%0,%1,%2,%3};"
        : "+f"(d[0]), "+f"(d[1]), "+f"(d[2]), "+f"(d[3])
        : "r"(a[0]), "r"(a[1]), "r"(a[2]), "r"(a[3]), "r"(b0), "r"(b1));
}
// first k-step: C = zero
__device__ __forceinline__ void mma8z(float* d, const uint32_t* a, uint32_t b0, uint32_t b1) {
    float z = 0.0f;
    asm volatile(
        "mma.sync.aligned.m16n8k8.row.col.f32.tf32.tf32.f32 "
        "{%0,%1,%2,%3}, {%4,%5,%6,%7}, {%8,%9}, {%10,%10,%10,%10};"
        : "=f"(d[0]), "=f"(d[1]), "=f"(d[2]), "=f"(d[3])
        : "r"(a[0]), "r"(a[1]), "r"(a[2]), "r"(a[3]), "r"(b0), "r"(b1), "f"(z));
}

// ---------------------------------------------------------------------------
// Kernel 1: build tf32-split, interleave-permuted rows.
// Logical K layout (56):
//   Q row: [0:16)=qhi  [16:32)=qhi  [32:48)=qlo  48=ahi 49=alo 50=1 51=1  pad 0
//   K row: [0:16)=khi  [16:32)=klo  [32:48)=khi  48=1  49=1  50=bhi 51=blo pad 0
// with q = inv*src_fea, k = (2*LOG2E*inv)*tgt_fea,
//      alpha = LOG2E*(F/blur^2 - |q|^2), beta = LOG2E*(G/blur^2 - |inv*tgt_fea|^2)
// Storage permutation: logical l = 8s + t + 4h  ->  pos p = 8s + 2t + h
// so a float2 at pos 8s+2t yields the (k=8s+t, k=8s+t+4) fragment pair.
// ---------------------------------------------------------------------------
__global__ void prep_kernel(const float* __restrict__ tgt,
                            const float* __restrict__ src_fea,
                            const float* __restrict__ tgt_fea,
                            const float* __restrict__ F_i,
                            const float* __restrict__ G_j) {
    int gidx = blockIdx.x * blockDim.x + threadIdx.x;
    const int total = BB * NN;
    const float inv = 1.0f / (1.41421356237f * BLUR);
    const float invb2 = 1.0f / (BLUR * BLUR);
    float vals[KDL];
#pragma unroll
    for (int i = 0; i < KDL; i++) vals[i] = 0.0f;

    float* dst;
    if (gidx < total) {
        const float4* sf = reinterpret_cast<const float4*>(src_fea) + gidx * 4;
        float q[16], x2 = 0.0f;
#pragma unroll
        for (int i = 0; i < 4; i++) {
            float4 v = sf[i];
            q[4*i+0] = inv*v.x; q[4*i+1] = inv*v.y; q[4*i+2] = inv*v.z; q[4*i+3] = inv*v.w;
            x2 += q[4*i]*q[4*i] + q[4*i+1]*q[4*i+1] + q[4*i+2]*q[4*i+2] + q[4*i+3]*q[4*i+3];
        }
        float alpha = LOG2E * (F_i[gidx] * invb2 - x2);
#pragma unroll
        for (int d = 0; d < 16; d++) {
            float hi = tf32r(q[d]);
            vals[d] = hi;
            vals[16 + d] = hi;
            vals[32 + d] = tf32r(q[d] - hi);
        }
        float ah = tf32r(alpha);
        vals[48] = ah;
        vals[49] = tf32r(alpha - ah);
        vals[50] = 1.0f;
        vals[51] = 1.0f;
        dst = g_A + (size_t)gidx * KDL;
    } else if (gidx < 2 * total) {
        int k = gidx - total;
        const float4* tf = reinterpret_cast<const float4*>(tgt_fea) + k * 4;
        float kv[16], y2 = 0.0f;
        const float ksc = 2.0f * LOG2E;
#pragma unroll
        for (int i = 0; i < 4; i++) {
            float4 v = tf[i];
            float y0 = inv*v.x, y1 = inv*v.y, y2v = inv*v.z, y3 = inv*v.w;
            y2 += y0*y0 + y1*y1 + y2v*y2v + y3*y3;
            kv[4*i+0] = ksc*y0; kv[4*i+1] = ksc*y1; kv[4*i+2] = ksc*y2v; kv[4*i+3] = ksc*y3;
        }
        float beta = LOG2E * (G_j[k] * invb2 - y2);
#pragma unroll
        for (int d = 0; d < 16; d++) {
            float hi = tf32r(kv[d]);
            vals[d] = hi;
            vals[16 + d] = tf32r(kv[d] - hi);
            vals[32 + d] = hi;
        }
        float bh = tf32r(beta);
        vals[48] = 1.0f;
        vals[49] = 1.0f;
        vals[50] = bh;
        vals[51] = tf32r(beta - bh);
        dst = g_B + (size_t)k * KDL;
        // Vaug: {1, vhi, 0, vlo}
        float v0 = tgt[k*3+0], v1 = tgt[k*3+1], v2 = tgt[k*3+2];
        float h0 = tf32r(v0), h1 = tf32r(v1), h2 = tf32r(v2);
        float* vd = g_V + (size_t)k * 8;
        vd[0] = 1.0f; vd[1] = h0; vd[2] = h1; vd[3] = h2;
        vd[4] = 0.0f; vd[5] = tf32r(v0 - h0); vd[6] = tf32r(v1 - h1); vd[7] = tf32r(v2 - h2);
    } else {
        return;
    }
    // permuted store
#pragma unroll
    for (int l = 0; l < KDL; l++) {
        int s = l >> 3, r = l & 7;
        int p = 8 * s + 2 * (r & 3) + (r >> 2);
        dst[p] = vals[l];
    }
}

// ---------------------------------------------------------------------------
// Kernel 2: flash OT attention via mma.sync tf32 (QK^T and P*Vaug both MMA).
// grid = BB * (NN/256) * KSPLIT = 128 CTAs, 256 threads (8 warps x m32).
// ---------------------------------------------------------------------------
#define BUFW (KC * RS + KC * 8)     // words per double-buffer slot (17408)
#define SMEM_BYTES (2 * BUFW * 4)   // 139264

__device__ __forceinline__ void copy_chunk(uint32_t sb, int buf, int b, int kbase) {
    const int tid = threadIdx.x;
    uint32_t dstB = sb + (uint32_t)buf * BUFW * 4;
    const float* srcB = g_B + ((size_t)b * MM + kbase) * KDL;
#pragma unroll
    for (int i = tid; i < KC * 14; i += TPB) {
        int row = i / 14, seg = i % 14;
        cpa16(dstB + (uint32_t)(row * RS + seg * 4) * 4, srcB + row * KDL + seg * 4);
    }
    uint32_t dstV = dstB + KC * RS * 4;
    const float* srcV = g_V + ((size_t)b * MM + kbase) * 8;
#pragma unroll
    for (int i = tid; i < KC * 2; i += TPB)
        cpa16(dstV + (uint32_t)i * 16, srcV + i * 4);
}

__global__ __launch_bounds__(TPB, 1) void flash_kernel() {
    extern __shared__ float smem[];
    const uint32_t sb = smem_u32(smem);
    const int tid = threadIdx.x;
    const int lane = tid & 31, wid = tid >> 5;
    const int g = lane >> 2, t = lane & 3;

    const int blk = blockIdx.x;
    const int split = blk & 1;
    const int qblk = (blk >> 1) & 15;
    const int b = blk >> 5;
    const int q0 = qblk * 256 + wid * 32;

    // A fragments for this warp's 32 query rows (2 m-blocks), kept in registers
    uint32_t a[2][7][4];
    {
        const float* gA = g_A + ((size_t)b * NN + q0) * KDL;
#pragma unroll
        for (int mb = 0; mb < 2; mb++)
#pragma unroll
            for (int s = 0; s < 7; s++) {
                float2 p0 = *(const float2*)(gA + (mb * 16 + g) * KDL + 8 * s + 2 * t);
                float2 p1 = *(const float2*)(gA + (mb * 16 + g + 8) * KDL + 8 * s + 2 * t);
                a[mb][s][0] = __float_as_uint(p0.x);
                a[mb][s][2] = __float_as_uint(p0.y);
                a[mb][s][1] = __float_as_uint(p1.x);
                a[mb][s][3] = __float_as_uint(p1.y);
            }
    }

    float pacc0[4] = {0.f, 0.f, 0.f, 0.f};
    float pacc1[4] = {0.f, 0.f, 0.f, 0.f};
    const int kb0 = split * (MM / KSPLIT);

    copy_chunk(sb, 0, b, kb0);
    CP_COMMIT();

    for (int ch = 0; ch < NCHK; ch++) {
        if (ch + 1 < NCHK) {
            copy_chunk(sb, (ch + 1) & 1, b, kb0 + (ch + 1) * KC);
            CP_COMMIT();
            CP_WAIT(1);
        } else {
            CP_WAIT(0);
        }
        __syncthreads();

        const float* Bs = smem + (ch & 1) * BUFW;
        const float* Vs = Bs + KC * RS;

        for (int n8 = 0; n8 < 32; n8++) {
            const float* Bt = Bs + (n8 * 8 + g) * RS + 2 * t;
            uint32_t bb[7][2];
#pragma unroll
            for (int s = 0; s < 7; s++) {
                float2 x = *(const float2*)(Bt + 8 * s);
                bb[s][0] = __float_as_uint(x.x);
                bb[s][1] = __float_as_uint(x.y);
            }
            const float* Vt = Vs + (n8 * 8 + 2 * t) * 8 + g;
            uint32_t v0 = __float_as_uint(Vt[0]);
            uint32_t v1 = __float_as_uint(Vt[8]);

            float d0[4], d1[4];
            mma8z(d0, a[0][0], bb[0][0], bb[0][1]);
            mma8z(d1, a[1][0], bb[0][0], bb[0][1]);
#pragma unroll
            for (int s = 1; s < 7; s++) {
                mma8(d0, a[0][s], bb[s][0], bb[s][1]);
                mma8(d1, a[1][s], bb[s][0], bb[s][1]);
            }
            // epilogue: P = exp2(logit) -> tf32, feed as A-frag {c0, c2, c1, c3}
            uint32_t e[4];
            e[0] = __float_as_uint(tf32r(ex2f(d0[0])));
            e[1] = __float_as_uint(tf32r(ex2f(d0[2])));
            e[2] = __float_as_uint(tf32r(ex2f(d0[1])));
            e[3] = __float_as_uint(tf32r(ex2f(d0[3])));
            mma8(pacc0, e, v0, v1);
            e[0] = __float_as_uint(tf32r(ex2f(d1[0])));
            e[1] = __float_as_uint(tf32r(ex2f(d1[2])));
            e[2] = __float_as_uint(tf32r(ex2f(d1[1])));
            e[3] = __float_as_uint(tf32r(ex2f(d1[3])));
            mma8(pacc1, e, v0, v1);
        }
        __syncthreads();
    }

    // combine hi/lo V columns (cols c and c+4) and write partials
#pragma unroll
    for (int mb = 0; mb < 2; mb++) {
        float* pa = mb ? pacc1 : pacc0;
        float s0 = pa[0] + __shfl_xor_sync(0xffffffffu, pa[0], 2);
        float s1 = pa[1] + __shfl_xor_sync(0xffffffffu, pa[1], 2);
        float s2 = pa[2] + __shfl_xor_sync(0xffffffffu, pa[2], 2);
        float s3 = pa[3] + __shfl_xor_sync(0xffffffffu, pa[3], 2);
        if (t < 2) {
            // t=0 -> (S, T0); t=1 -> (T1, T2)
            int row = q0 + mb * 16 + g;
            size_t idx4 = ((size_t)(split * BB + b)) * NN + row;
            float2* dst = reinterpret_cast<float2*>(g_st);
            dst[idx4 * 2 + t] = make_float2(s0, s1);
            dst[(idx4 + 8) * 2 + t] = make_float2(s2, s3);
        }
    }
}

// ---------------------------------------------------------------------------
// Kernel 3: per-batch reduction (fp32 partials, fp64 tree) + 3x3 SVD + Kabsch
// (reference's row-scaled reflection handling: R = diag(1,1,sgn) * U V^T).
// ---------------------------------------------------------------------------
__global__ __launch_bounds__(256) void reduce_svd_kernel(
    const float* __restrict__ src, float* __restrict__ out) {
    const int b = blockIdx.x;
    float acc[23];
#pragma unroll
    for (int i = 0; i < 23; i++) acc[i] = 0.0f;

    for (int n = threadIdx.x; n < NN; n += 256) {
        float S = 0.f, T0 = 0.f, T1 = 0.f, T2 = 0.f;
#pragma unroll
        for (int c = 0; c < KSPLIT; c++) {
            float4 p = g_st[((size_t)(c * BB + b)) * NN + n];
            S += p.x; T0 += p.y; T1 += p.z; T2 += p.w;
        }
        float x0 = src[(b * NN + n) * 3 + 0];
        float x1 = src[(b * NN + n) * 3 + 1];
        float x2 = src[(b * NN + n) * 3 + 2];
        float S2 = S * S;
        acc[0] += S;
        acc[1] += S * x0;  acc[2] += S * x1;  acc[3] += S * x2;
        acc[4] += T0;      acc[5] += T1;      acc[6] += T2;
        acc[7] += S2;
        acc[8] += S2 * x0; acc[9] += S2 * x1; acc[10] += S2 * x2;
        acc[11] += S * T0; acc[12] += S * T1; acc[13] += S * T2;
        acc[14] += S * T0 * x0; acc[15] += S * T0 * x1; acc[16] += S * T0 * x2;
        acc[17] += S * T1 * x0; acc[18] += S * T1 * x1; acc[19] += S * T1 * x2;
        acc[20] += S * T2 * x0; acc[21] += S * T2 * x1; acc[22] += S * T2 * x2;
    }

    __shared__ double red[256];
    __shared__ double tot[23];
    for (int qd = 0; qd < 23; qd++) {
        red[threadIdx.x] = (double)acc[qd];
        __syncthreads();
        for (int s = 128; s > 0; s >>= 1) {
            if (threadIdx.x < s) red[threadIdx.x] += red[threadIdx.x + s];
            __syncthreads();
        }
        if (threadIdx.x == 0) tot[qd] = red[0];
        __syncthreads();
    }

    if (threadIdx.x == 0) {
        double Sw = tot[0];
        double mux[3] = {tot[1] / Sw, tot[2] / Sw, tot[3] / Sw};
        double muy[3] = {tot[4] / Sw, tot[5] / Sw, tot[6] / Sw};
        double S2 = tot[7];
        double S2x[3] = {tot[8], tot[9], tot[10]};
        double STp[3] = {tot[11], tot[12], tot[13]};
        double A[3][3];
        for (int d = 0; d < 3; d++)
            for (int e = 0; e < 3; e++)
                A[d][e] = tot[14 + 3 * d + e] - mux[e] * STp[d]
                        - muy[d] * S2x[e] + muy[d] * mux[e] * S2;

        double detA =
            A[0][0] * (A[1][1] * A[2][2] - A[1][2] * A[2][1])
          - A[0][1] * (A[1][0] * A[2][2] - A[1][2] * A[2][0])
          + A[0][2] * (A[1][0] * A[2][1] - A[1][1] * A[2][0]);
        double sgn = (detA >= 0.0) ? 1.0 : -1.0;

        double C[3][3];
        for (int i = 0; i < 3; i++)
            for (int j = 0; j < 3; j++) {
                double s = 0.0;
                for (int d = 0; d < 3; d++) s += A[d][i] * A[d][j];
                C[i][j] = s;
            }
        double V[3][3] = {{1,0,0},{0,1,0},{0,0,1}};
        const int pq[3][2] = {{0,1},{0,2},{1,2}};
        for (int sweep = 0; sweep < 15; sweep++) {
            for (int r = 0; r < 3; r++) {
                int p = pq[r][0], q = pq[r][1];
                double apq = C[p][q];
                if (fabs(apq) < 1e-30) continue;
                double theta = (C[q][q] - C[p][p]) / (2.0 * apq);
                double tt = (theta >= 0.0 ? 1.0 : -1.0) /
                            (fabs(theta) + sqrt(1.0 + theta * theta));
                double c = 1.0 / sqrt(1.0 + tt * tt);
                double s = tt * c;
                for (int k = 0; k < 3; k++) {
                    double ckp = C[k][p], ckq = C[k][q];
                    C[k][p] = c * ckp - s * ckq;
                    C[k][q] = s * ckp + c * ckq;
                }
                for (int k = 0; k < 3; k++) {
                    double cpk = C[p][k], cqk = C[q][k];
                    C[p][k] = c * cpk - s * cqk;
                    C[q][k] = s * cpk + c * cqk;
                }
                for (int k = 0; k < 3; k++) {
                    double vkp = V[k][p], vkq = V[k][q];
                    V[k][p] = c * vkp - s * vkq;
                    V[k][q] = s * vkp + c * vkq;
                }
            }
        }
        double ev[3] = {C[0][0], C[1][1], C[2][2]};
        int i0 = 0;
        if (ev[1] > ev[i0]) i0 = 1;
        if (ev[2] > ev[i0]) i0 = 2;
        int i2 = 0;
        if (ev[1] < ev[i2]) i2 = 1;
        if (ev[2] < ev[i2]) i2 = 2;
        if (i2 == i0) i2 = (i0 + 1) % 3;
        int i1 = 3 - i0 - i2;

        double v1[3] = {V[0][i0], V[1][i0], V[2][i0]};
        double v2[3] = {V[0][i1], V[1][i1], V[2][i1]};
        double u1[3], u2[3];
        for (int d = 0; d < 3; d++)
            u1[d] = A[d][0] * v1[0] + A[d][1] * v1[1] + A[d][2] * v1[2];
        double n1 = sqrt(u1[0]*u1[0] + u1[1]*u1[1] + u1[2]*u1[2]);
        for (int d = 0; d < 3; d++) u1[d] /= n1;
        for (int d = 0; d < 3; d++)
            u2[d] = A[d][0] * v2[0] + A[d][1] * v2[1] + A[d][2] * v2[2];
        double dp = u1[0]*u2[0] + u1[1]*u2[1] + u1[2]*u2[2];
        for (int d = 0; d < 3; d++) u2[d] -= dp * u1[d];
        double n2 = sqrt(u2[0]*u2[0] + u2[1]*u2[1] + u2[2]*u2[2]);
        for (int d = 0; d < 3; d++) u2[d] /= n2;
        double u3[3] = {u1[1]*u2[2] - u1[2]*u2[1],
                        u1[2]*u2[0] - u1[0]*u2[2],
                        u1[0]*u2[1] - u1[1]*u2[0]};
        double v3[3] = {v1[1]*v2[2] - v1[2]*v2[1],
                        v1[2]*v2[0] - v1[0]*v2[2],
                        v1[0]*v2[1] - v1[1]*v2[0]};
        double UV[3][3];
        for (int d = 0; d < 3; d++)
            for (int e = 0; e < 3; e++)
                UV[d][e] = u1[d]*v1[e] + u2[d]*v2[e] + sgn * u3[d]*v3[e];
        double R[3][3];
        for (int d = 0; d < 3; d++) {
            double rs = (d == 2) ? sgn : 1.0;
            for (int e = 0; e < 3; e++) R[d][e] = rs * UV[d][e];
        }
        double tvec[3];
        for (int d = 0; d < 3; d++)
            tvec[d] = muy[d] - (R[d][0]*mux[0] + R[d][1]*mux[1] + R[d][2]*mux[2]);

        for (int d = 0; d < 3; d++)
            for (int e = 0; e < 3; e++)
                out[b * 9 + d * 3 + e] = (float)R[d][e];
        for (int d = 0; d < 3; d++)
            out[BB * 9 + b * 3 + d] = (float)tvec[d];
    }
}

extern "C" void kernel_launch(void* const* d_in, const int* in_sizes, int n_in,
                              void* d_out, int out_size) {
    const float* src     = (const float*)d_in[0];
    const float* tgt     = (const float*)d_in[1];
    const float* src_fea = (const float*)d_in[2];
    const float* tgt_fea = (const float*)d_in[3];
    const float* F_i     = (const float*)d_in[4];
    const float* G_j     = (const float*)d_in[5];
    float* out = (float*)d_out;

    cudaFuncSetAttribute(flash_kernel,
                         cudaFuncAttributeMaxDynamicSharedMemorySize, SMEM_BYTES);

    prep_kernel<<<(2 * BB * NN + TPB - 1) / TPB, TPB>>>(tgt, src_fea, tgt_fea, F_i, G_j);
    flash_kernel<<<BB * (NN / 256) * KSPLIT, TPB, SMEM_BYTES>>>();
    reduce_svd_kernel<<<BB, 256>>>(src, out);
}